// round 2
// baseline (speedup 1.0000x reference)
#include <cuda_runtime.h>
#include <cstdint>
#include <math.h>

#define NE 8
#define NTOK 16384
#define DIM 1024
#define FF 2048

// ---------------- scratch (device globals; no allocation) ----------------
__device__ int   g_counts[NE];
__device__ int   g_offsets[NE + 1];
__device__ int   g_tok[NE * NTOK];
__device__ float g_cw[NE * NTOK];
__device__ float g_H[(size_t)2 * NTOK * FF];   // 256 MiB hidden activations

// ---------------- helpers ----------------
__device__ __forceinline__ unsigned f2tf(float f) {
    unsigned u;
    asm("cvt.rna.tf32.f32 %0, %1;" : "=r"(u) : "f"(f));
    return u;
}
__device__ __forceinline__ float f2tf_f(float f) { return __uint_as_float(f2tf(f)); }

__device__ __forceinline__ void mma8(float* c, const float* a, const float* b) {
    asm volatile(
        "mma.sync.aligned.m16n8k8.row.col.f32.tf32.tf32.f32 "
        "{%0,%1,%2,%3},{%4,%5,%6,%7},{%8,%9},{%0,%1,%2,%3};"
        : "+f"(c[0]), "+f"(c[1]), "+f"(c[2]), "+f"(c[3])
        : "r"(__float_as_uint(a[0])), "r"(__float_as_uint(a[1])),
          "r"(__float_as_uint(a[2])), "r"(__float_as_uint(a[3])),
          "r"(__float_as_uint(b[0])), "r"(__float_as_uint(b[1])));
}

// fragment-order SMEM offsets (values stored pre-converted to tf32)
// A-frag: per (kk2, 16-row block): [lane][4] ; one LDS.128 per frag read
__device__ __forceinline__ int a_off(int row, int k) {
    return (((k >> 3) * 8 + (row >> 4)) * 32 + (((row & 7) << 2) | (k & 3))) * 4
           + ((row >> 3) & 1) + (((k >> 2) & 1) << 1);
}
// B-frag: per (kk2, 8-col block): [lane][2] ; one LDS.64 per frag read
template <int NB8>
__device__ __forceinline__ int b_off(int col, int k) {
    return (((k >> 3) * NB8 + (col >> 3)) * 32 + (((col & 7) << 2) | (k & 3))) * 2
           + ((k >> 2) & 1);
}

// ---------------- kernel 0: zero output + counts ----------------
__global__ void zero_kernel(float* out, int n) {
    int i = blockIdx.x * blockDim.x + threadIdx.x;
    if (i < n) out[i] = 0.0f;
    if (blockIdx.x == 0 && threadIdx.x < NE) g_counts[threadIdx.x] = 0;
}

// ---------------- kernel 1: gating + routing (one warp per token) ----------------
__global__ void gate_kernel(const float* __restrict__ x, const float* __restrict__ gw) {
    int warp = threadIdx.x >> 5;
    int lane = threadIdx.x & 31;
    int token = blockIdx.x * 8 + warp;

    const float* xr = x + (size_t)token * DIM;
    float xv[32];
#pragma unroll
    for (int j = 0; j < 32; j++) xv[j] = xr[j * 32 + lane];

    float logits[NE];
#pragma unroll
    for (int e = 0; e < NE; e++) {
        const float* g = gw + e * DIM;
        float s = 0.0f;
#pragma unroll
        for (int j = 0; j < 32; j++) s += xv[j] * g[j * 32 + lane];
#pragma unroll
        for (int o = 16; o; o >>= 1) s += __shfl_xor_sync(0xffffffffu, s, o);
        logits[e] = s;
    }

    if (lane == 0) {
        int i1 = 0;
#pragma unroll
        for (int e = 1; e < NE; e++)
            if (logits[e] > logits[i1]) i1 = e;
        int i2 = -1;
#pragma unroll
        for (int e = 0; e < NE; e++) {
            if (e == i1) continue;
            if (i2 < 0 || logits[e] > logits[i2]) i2 = e;
        }
        float p1 = 1.0f / (1.0f + __expf(logits[i2] - logits[i1]));
        float p2 = 1.0f - p1;
        int s1 = atomicAdd(&g_counts[i1], 1);
        g_tok[i1 * NTOK + s1] = token;
        g_cw[i1 * NTOK + s1]  = p1;
        int s2 = atomicAdd(&g_counts[i2], 1);
        g_tok[i2 * NTOK + s2] = token;
        g_cw[i2 * NTOK + s2]  = p2;
    }
}

// ---------------- kernel 2: prefix over 8 counts ----------------
__global__ void prefix_kernel() {
    if (threadIdx.x == 0) {
        int a = 0;
        for (int e = 0; e < NE; e++) { g_offsets[e] = a; a += g_counts[e]; }
        g_offsets[NE] = a;
    }
}

// ---------------- tile scheduler ----------------
__device__ __forceinline__ bool find_tile(int bx, int& e, int& tile, int& cnt) {
    int acc = 0;
    e = -1;
#pragma unroll
    for (int ee = 0; ee < NE; ee++) {
        int c = g_counts[ee];
        int t = (c + 127) >> 7;
        if (e < 0 && bx < acc + t) { e = ee; tile = bx - acc; cnt = c; }
        acc += t;
    }
    return e >= 0;
}

// ---------------- kernel 3: GEMM1 (x@w1^T, x@w3^T) -> silu*mul -> H ----------------
// BM=128, BN=64 (dual B), BK=16, double-buffered frag-order SMEM
__global__ __launch_bounds__(256, 2) void gemm1_kernel(const float* __restrict__ x,
                                                       const float* __restrict__ w1,
                                                       const float* __restrict__ w3) {
    int e, tile, cnt;
    if (!find_tile(blockIdx.x, e, tile, cnt)) return;
    int offs = g_offsets[e];
    int n0 = blockIdx.y * 64;

    __shared__ float As[2][2048];
    __shared__ float B1s[2][1024];
    __shared__ float B3s[2][1024];
    __shared__ int   stok[128];

    int tid = threadIdx.x;
    if (tid < 128) {
        int i = tile * 128 + tid;
        stok[tid] = (i < cnt) ? g_tok[e * NTOK + i] : -1;
    }
    __syncthreads();

    int warp = tid >> 5, lane = tid & 31;
    int wm = warp >> 1, wn = warp & 1;

    // fixed per-thread load coordinates
    int ar0 = tid >> 2;                    // A rows 0..63
    int ar1 = (tid + 256) >> 2;            // A rows 64..127
    int ac4 = (tid & 3) << 2;
    int t0 = stok[ar0], t1 = stok[ar1];
    const float* ap0 = x + (size_t)(t0 < 0 ? 0 : t0) * DIM + ac4;
    const float* ap1 = x + (size_t)(t1 < 0 ? 0 : t1) * DIM + ac4;
    int br = tid >> 2;
    int bc4 = (tid & 3) << 2;
    const float* b1p = w1 + (size_t)e * FF * DIM + (size_t)(n0 + br) * DIM + bc4;
    const float* b3p = w3 + (size_t)e * FF * DIM + (size_t)(n0 + br) * DIM + bc4;

    float4 ra0, ra1, rb1, rb3;
    auto load_k = [&](int k0) {
        ra0 = (t0 >= 0) ? *(const float4*)(ap0 + k0) : make_float4(0.f, 0.f, 0.f, 0.f);
        ra1 = (t1 >= 0) ? *(const float4*)(ap1 + k0) : make_float4(0.f, 0.f, 0.f, 0.f);
        rb1 = *(const float4*)(b1p + k0);
        rb3 = *(const float4*)(b3p + k0);
    };
    auto store_stage = [&](int s) {
        float* A = As[s];
        A[a_off(ar0, ac4 + 0)] = f2tf_f(ra0.x);
        A[a_off(ar0, ac4 + 1)] = f2tf_f(ra0.y);
        A[a_off(ar0, ac4 + 2)] = f2tf_f(ra0.z);
        A[a_off(ar0, ac4 + 3)] = f2tf_f(ra0.w);
        A[a_off(ar1, ac4 + 0)] = f2tf_f(ra1.x);
        A[a_off(ar1, ac4 + 1)] = f2tf_f(ra1.y);
        A[a_off(ar1, ac4 + 2)] = f2tf_f(ra1.z);
        A[a_off(ar1, ac4 + 3)] = f2tf_f(ra1.w);
        float* B1 = B1s[s];
        B1[b_off<8>(br, bc4 + 0)] = f2tf_f(rb1.x);
        B1[b_off<8>(br, bc4 + 1)] = f2tf_f(rb1.y);
        B1[b_off<8>(br, bc4 + 2)] = f2tf_f(rb1.z);
        B1[b_off<8>(br, bc4 + 3)] = f2tf_f(rb1.w);
        float* B3 = B3s[s];
        B3[b_off<8>(br, bc4 + 0)] = f2tf_f(rb3.x);
        B3[b_off<8>(br, bc4 + 1)] = f2tf_f(rb3.y);
        B3[b_off<8>(br, bc4 + 2)] = f2tf_f(rb3.z);
        B3[b_off<8>(br, bc4 + 3)] = f2tf_f(rb3.w);
    };

    float acc1[2][4][4] = {};
    float acc3[2][4][4] = {};

    auto compute_stage = [&](int s) {
#pragma unroll
        for (int kk2 = 0; kk2 < 2; kk2++) {
            float4 af[2];
#pragma unroll
            for (int mt = 0; mt < 2; mt++)
                af[mt] = *(const float4*)&As[s][((kk2 * 8 + wm * 2 + mt) * 32 + lane) * 4];
#pragma unroll
            for (int nt = 0; nt < 4; nt++) {
                int n8 = wn * 4 + nt;
                float2 b1 = *(const float2*)&B1s[s][((kk2 * 8 + n8) * 32 + lane) * 2];
                float2 b3 = *(const float2*)&B3s[s][((kk2 * 8 + n8) * 32 + lane) * 2];
#pragma unroll
                for (int mt = 0; mt < 2; mt++) {
                    mma8(acc1[mt][nt], (const float*)&af[mt], (const float*)&b1);
                    mma8(acc3[mt][nt], (const float*)&af[mt], (const float*)&b3);
                }
            }
        }
    };

    load_k(0);
    store_stage(0);
    __syncthreads();
#pragma unroll 1
    for (int kt = 0; kt < DIM / 16; kt++) {
        int cur = kt & 1;
        if (kt + 1 < DIM / 16) load_k((kt + 1) * 16);
        compute_stage(cur);
        if (kt + 1 < DIM / 16) store_stage(cur ^ 1);
        __syncthreads();
    }

    // epilogue: h = silu(s1) * s3 -> g_H
#pragma unroll
    for (int mt = 0; mt < 2; mt++) {
#pragma unroll
        for (int nt = 0; nt < 4; nt++) {
#pragma unroll
            for (int q = 0; q < 4; q++) {
                int r  = wm * 32 + mt * 16 + (lane >> 2) + ((q >= 2) ? 8 : 0);
                int cc = wn * 32 + nt * 8 + ((lane & 3) << 1) + (q & 1);
                int i = tile * 128 + r;
                if (i < cnt) {
                    float s1 = acc1[mt][nt][q], s3 = acc3[mt][nt][q];
                    float h = (s1 / (1.0f + __expf(-s1))) * s3;
                    g_H[(size_t)(offs + i) * FF + n0 + cc] = h;
                }
            }
        }
    }
}

// ---------------- kernel 4: GEMM2 (H @ w2^T), BN=128, scaled scatter-add ----------------
__global__ __launch_bounds__(256, 2) void gemm2_kernel(const float* __restrict__ w2,
                                                       float* __restrict__ out) {
    int e, tile, cnt;
    if (!find_tile(blockIdx.x, e, tile, cnt)) return;
    int offs = g_offsets[e];
    int n0 = blockIdx.y * 128;

    __shared__ float As[2][2048];
    __shared__ float Bs[2][2048];
    __shared__ int   stok[128];
    __shared__ float scw[128];

    int tid = threadIdx.x;
    if (tid < 128) {
        int i = tile * 128 + tid;
        stok[tid] = (i < cnt) ? g_tok[e * NTOK + i] : -1;
        scw[tid]  = (i < cnt) ? g_cw[e * NTOK + i] : 0.0f;
    }
    __syncthreads();

    int warp = tid >> 5, lane = tid & 31;
    int wm = warp >> 1, wn = warp & 1;

    // fixed per-thread load coordinates
    int ar0 = tid >> 2;
    int ar1 = (tid + 256) >> 2;
    int ac4 = (tid & 3) << 2;
    bool av0 = (tile * 128 + ar0) < cnt;
    bool av1 = (tile * 128 + ar1) < cnt;
    const float* ap0 = g_H + (size_t)(offs + tile * 128 + (av0 ? ar0 : 0)) * FF + ac4;
    const float* ap1 = g_H + (size_t)(offs + tile * 128 + (av1 ? ar1 : 0)) * FF + ac4;
    int br0 = tid >> 2;               // B rows 0..63
    int br1 = (tid + 256) >> 2;       // B rows 64..127
    int bc4 = (tid & 3) << 2;
    const float* bp0 = w2 + (size_t)e * DIM * FF + (size_t)(n0 + br0) * FF + bc4;
    const float* bp1 = w2 + (size_t)e * DIM * FF + (size_t)(n0 + br1) * FF + bc4;

    float4 ra0, ra1, rb0, rb1;
    auto load_k = [&](int k0) {
        ra0 = av0 ? *(const float4*)(ap0 + k0) : make_float4(0.f, 0.f, 0.f, 0.f);
        ra1 = av1 ? *(const float4*)(ap1 + k0) : make_float4(0.f, 0.f, 0.f, 0.f);
        rb0 = *(const float4*)(bp0 + k0);
        rb1 = *(const float4*)(bp1 + k0);
    };
    auto store_stage = [&](int s) {
        float* A = As[s];
        A[a_off(ar0, ac4 + 0)] = f2tf_f(ra0.x);
        A[a_off(ar0, ac4 + 1)] = f2tf_f(ra0.y);
        A[a_off(ar0, ac4 + 2)] = f2tf_f(ra0.z);
        A[a_off(ar0, ac4 + 3)] = f2tf_f(ra0.w);
        A[a_off(ar1, ac4 + 0)] = f2tf_f(ra1.x);
        A[a_off(ar1, ac4 + 1)] = f2tf_f(ra1.y);
        A[a_off(ar1, ac4 + 2)] = f2tf_f(ra1.z);
        A[a_off(ar1, ac4 + 3)] = f2tf_f(ra1.w);
        float* B = Bs[s];
        B[b_off<16>(br0, bc4 + 0)] = f2tf_f(rb0.x);
        B[b_off<16>(br0, bc4 + 1)] = f2tf_f(rb0.y);
        B[b_off<16>(br0, bc4 + 2)] = f2tf_f(rb0.z);
        B[b_off<16>(br0, bc4 + 3)] = f2tf_f(rb0.w);
        B[b_off<16>(br1, bc4 + 0)] = f2tf_f(rb1.x);
        B[b_off<16>(br1, bc4 + 1)] = f2tf_f(rb1.y);
        B[b_off<16>(br1, bc4 + 2)] = f2tf_f(rb1.z);
        B[b_off<16>(br1, bc4 + 3)] = f2tf_f(rb1.w);
    };

    float acc[2][8][4] = {};

    auto compute_stage = [&](int s) {
#pragma unroll
        for (int kk2 = 0; kk2 < 2; kk2++) {
            float4 af[2];
#pragma unroll
            for (int mt = 0; mt < 2; mt++)
                af[mt] = *(const float4*)&As[s][((kk2 * 8 + wm * 2 + mt) * 32 + lane) * 4];
#pragma unroll
            for (int nt = 0; nt < 8; nt++) {
                int n8 = wn * 8 + nt;
                float2 b = *(const float2*)&Bs[s][((kk2 * 16 + n8) * 32 + lane) * 2];
#pragma unroll
                for (int mt = 0; mt < 2; mt++)
                    mma8(acc[mt][nt], (const float*)&af[mt], (const float*)&b);
            }
        }
    };

    load_k(0);
    store_stage(0);
    __syncthreads();
#pragma unroll 1
    for (int kt = 0; kt < FF / 16; kt++) {
        int cur = kt & 1;
        if (kt + 1 < FF / 16) load_k((kt + 1) * 16);
        compute_stage(cur);
        if (kt + 1 < FF / 16) store_stage(cur ^ 1);
        __syncthreads();
    }

    // epilogue: out[token, n] += cw * acc  (2 commutative adds/elem -> deterministic)
#pragma unroll
    for (int mt = 0; mt < 2; mt++) {
#pragma unroll
        for (int nt = 0; nt < 8; nt++) {
#pragma unroll
            for (int q = 0; q < 4; q++) {
                int r  = wm * 32 + mt * 16 + (lane >> 2) + ((q >= 2) ? 8 : 0);
                int cc = wn * 64 + nt * 8 + ((lane & 3) << 1) + (q & 1);
                int i = tile * 128 + r;
                if (i < cnt) {
                    int t  = stok[r];
                    float w = scw[r];
                    atomicAdd(&out[(size_t)t * DIM + n0 + cc], acc[mt][nt][q] * w);
                }
            }
        }
    }
}

// ---------------- launch ----------------
extern "C" void kernel_launch(void* const* d_in, const int* in_sizes, int n_in,
                              void* d_out, int out_size) {
    const float* x  = (const float*)d_in[0];
    const float* gw = (const float*)d_in[1];
    const float* w1 = (const float*)d_in[2];
    const float* w2 = (const float*)d_in[3];
    const float* w3 = (const float*)d_in[4];
    float* out = (float*)d_out;

    zero_kernel<<<(out_size + 255) / 256, 256>>>(out, out_size);
    gate_kernel<<<NTOK / 8, 256>>>(x, gw);
    prefix_kernel<<<1, 32>>>();
    gemm1_kernel<<<dim3(264, FF / 64), 256>>>(x, w1, w3);
    gemm2_kernel<<<dim3(264, DIM / 128), 256>>>(w2, out);
}

// round 4
// speedup vs baseline: 1.7027x; 1.7027x over previous
#include <cuda_runtime.h>
#include <cstdint>
#include <math.h>

#define NE 8
#define NTOK 16384
#define DIM 1024
#define FF 2048

// ---------------- scratch (device globals; no allocation) ----------------
__device__ int   g_counts[NE];
__device__ int   g_offsets[NE + 1];
__device__ int   g_tok[NE * NTOK];
__device__ float g_cw[NE * NTOK];
__device__ float g_H[(size_t)2 * NTOK * FF];   // 256 MiB hidden activations

// ---------------- helpers ----------------
__device__ __forceinline__ unsigned f2tf(float f) {
    unsigned u;
    asm("cvt.rna.tf32.f32 %0, %1;" : "=r"(u) : "f"(f));
    return u;
}
__device__ __forceinline__ float f2tf_f(float f) { return __uint_as_float(f2tf(f)); }
__device__ __forceinline__ float4 cvt4(float4 v) {
    float4 r;
    r.x = f2tf_f(v.x); r.y = f2tf_f(v.y); r.z = f2tf_f(v.z); r.w = f2tf_f(v.w);
    return r;
}

__device__ __forceinline__ void mma8(float* c, const float* a, const float* b) {
    asm volatile(
        "mma.sync.aligned.m16n8k8.row.col.f32.tf32.tf32.f32 "
        "{%0,%1,%2,%3},{%4,%5,%6,%7},{%8,%9},{%0,%1,%2,%3};"
        : "+f"(c[0]), "+f"(c[1]), "+f"(c[2]), "+f"(c[3])
        : "r"(__float_as_uint(a[0])), "r"(__float_as_uint(a[1])),
          "r"(__float_as_uint(a[2])), "r"(__float_as_uint(a[3])),
          "r"(__float_as_uint(b[0])), "r"(__float_as_uint(b[1])));
}

// XOR-swizzled SMEM index: 16-float rows, conflict-free STS.128, <=2-way LDS.32
__device__ __forceinline__ int swz(int r, int c) {
    return r * 16 + (c ^ ((r & 3) << 2));
}

// ---------------- kernel 0: zero output + counts ----------------
__global__ void zero_kernel(float* out, int n) {
    int i = blockIdx.x * blockDim.x + threadIdx.x;
    if (i < n) out[i] = 0.0f;
    if (blockIdx.x == 0 && threadIdx.x < NE) g_counts[threadIdx.x] = 0;
}

// ---------------- kernel 1: gating + routing (one warp per token) ----------------
__global__ void gate_kernel(const float* __restrict__ x, const float* __restrict__ gw) {
    int warp = threadIdx.x >> 5;
    int lane = threadIdx.x & 31;
    int token = blockIdx.x * 8 + warp;

    const float* xr = x + (size_t)token * DIM;
    float xv[32];
#pragma unroll
    for (int j = 0; j < 32; j++) xv[j] = xr[j * 32 + lane];

    float logits[NE];
#pragma unroll
    for (int e = 0; e < NE; e++) {
        const float* g = gw + e * DIM;
        float s = 0.0f;
#pragma unroll
        for (int j = 0; j < 32; j++) s += xv[j] * g[j * 32 + lane];
#pragma unroll
        for (int o = 16; o; o >>= 1) s += __shfl_xor_sync(0xffffffffu, s, o);
        logits[e] = s;
    }

    if (lane == 0) {
        int i1 = 0;
#pragma unroll
        for (int e = 1; e < NE; e++)
            if (logits[e] > logits[i1]) i1 = e;
        int i2 = -1;
#pragma unroll
        for (int e = 0; e < NE; e++) {
            if (e == i1) continue;
            if (i2 < 0 || logits[e] > logits[i2]) i2 = e;
        }
        float p1 = 1.0f / (1.0f + __expf(logits[i2] - logits[i1]));
        float p2 = 1.0f - p1;
        int s1 = atomicAdd(&g_counts[i1], 1);
        g_tok[i1 * NTOK + s1] = token;
        g_cw[i1 * NTOK + s1]  = p1;
        int s2 = atomicAdd(&g_counts[i2], 1);
        g_tok[i2 * NTOK + s2] = token;
        g_cw[i2 * NTOK + s2]  = p2;
    }
}

// ---------------- kernel 2: prefix over 8 counts ----------------
__global__ void prefix_kernel() {
    if (threadIdx.x == 0) {
        int a = 0;
        for (int e = 0; e < NE; e++) { g_offsets[e] = a; a += g_counts[e]; }
        g_offsets[NE] = a;
    }
}

// ---------------- tile scheduler ----------------
__device__ __forceinline__ bool find_tile(int bx, int& e, int& tile, int& cnt) {
    int acc = 0;
    e = -1;
#pragma unroll
    for (int ee = 0; ee < NE; ee++) {
        int c = g_counts[ee];
        int t = (c + 127) >> 7;
        if (e < 0 && bx < acc + t) { e = ee; tile = bx - acc; cnt = c; }
        acc += t;
    }
    return e >= 0;
}

// ---------------- kernel 3: GEMM1 (x@w1^T, x@w3^T) -> silu*mul -> H ----------------
// BM=128, BN=64 (dual B), BK=16; double-buffered, tf32-converted swizzled SMEM
__global__ __launch_bounds__(256, 2) void gemm1_kernel(const float* __restrict__ x,
                                                       const float* __restrict__ w1,
                                                       const float* __restrict__ w3) {
    int e, tile, cnt;
    if (!find_tile(blockIdx.x, e, tile, cnt)) return;
    int offs = g_offsets[e];
    int n0 = blockIdx.y * 64;

    __shared__ float As[2][2048];
    __shared__ float B1s[2][1024];
    __shared__ float B3s[2][1024];
    __shared__ int   stok[128];

    int tid = threadIdx.x;
    if (tid < 128) {
        int i = tile * 128 + tid;
        stok[tid] = (i < cnt) ? g_tok[e * NTOK + i] : -1;
    }
    __syncthreads();

    int warp = tid >> 5, lane = tid & 31;
    int wm = warp >> 1, wn = warp & 1;

    // per-thread load coordinates
    int ar0 = tid >> 2;                 // A rows 0..63
    int ar1 = ar0 + 64;                 // A rows 64..127
    int ac4 = (tid & 3) << 2;
    int t0 = stok[ar0], t1 = stok[ar1];
    const float* ap0 = x + (size_t)(t0 < 0 ? 0 : t0) * DIM + ac4;
    const float* ap1 = x + (size_t)(t1 < 0 ? 0 : t1) * DIM + ac4;
    int br = tid >> 2;                  // B rows 0..63
    const float* b1p = w1 + (size_t)e * FF * DIM + (size_t)(n0 + br) * DIM + ac4;
    const float* b3p = w3 + (size_t)e * FF * DIM + (size_t)(n0 + br) * DIM + ac4;

    float4 ra0, ra1, rb1, rb3;
    auto load_k = [&](int k0) {
        ra0 = (t0 >= 0) ? *(const float4*)(ap0 + k0) : make_float4(0.f, 0.f, 0.f, 0.f);
        ra1 = (t1 >= 0) ? *(const float4*)(ap1 + k0) : make_float4(0.f, 0.f, 0.f, 0.f);
        rb1 = *(const float4*)(b1p + k0);
        rb3 = *(const float4*)(b3p + k0);
    };
    auto store_stage = [&](int s) {
        *(float4*)&As[s][swz(ar0, ac4)]  = cvt4(ra0);
        *(float4*)&As[s][swz(ar1, ac4)]  = cvt4(ra1);
        *(float4*)&B1s[s][swz(br, ac4)]  = cvt4(rb1);
        *(float4*)&B3s[s][swz(br, ac4)]  = cvt4(rb3);
    };

    float acc1[2][4][4] = {};
    float acc3[2][4][4] = {};

    auto compute_stage = [&](int s) {
        const float* A  = As[s];
        const float* B1 = B1s[s];
        const float* B3 = B3s[s];
#pragma unroll
        for (int kk = 0; kk < 16; kk += 8) {
            float a[2][4];
#pragma unroll
            for (int mt = 0; mt < 2; mt++) {
                int r0 = wm * 32 + mt * 16 + (lane >> 2);
                int c  = kk + (lane & 3);
                a[mt][0] = A[swz(r0, c)];
                a[mt][1] = A[swz(r0 + 8, c)];
                a[mt][2] = A[swz(r0, c + 4)];
                a[mt][3] = A[swz(r0 + 8, c + 4)];
            }
#pragma unroll
            for (int nt = 0; nt < 4; nt++) {
                int cn = wn * 32 + nt * 8 + (lane >> 2);
                int kr = kk + (lane & 3);
                float b1[2], b3[2];
                b1[0] = B1[swz(cn, kr)]; b1[1] = B1[swz(cn, kr + 4)];
                b3[0] = B3[swz(cn, kr)]; b3[1] = B3[swz(cn, kr + 4)];
#pragma unroll
                for (int mt = 0; mt < 2; mt++) {
                    mma8(acc1[mt][nt], a[mt], b1);
                    mma8(acc3[mt][nt], a[mt], b3);
                }
            }
        }
    };

    load_k(0);
    store_stage(0);
    __syncthreads();
#pragma unroll 1
    for (int kt = 0; kt < DIM / 16; kt++) {
        int cur = kt & 1;
        if (kt + 1 < DIM / 16) load_k((kt + 1) * 16);
        compute_stage(cur);
        if (kt + 1 < DIM / 16) store_stage(cur ^ 1);
        __syncthreads();
    }

    // epilogue: h = silu(s1) * s3 -> g_H
#pragma unroll
    for (int mt = 0; mt < 2; mt++) {
#pragma unroll
        for (int nt = 0; nt < 4; nt++) {
#pragma unroll
            for (int q = 0; q < 4; q++) {
                int r  = wm * 32 + mt * 16 + (lane >> 2) + ((q >= 2) ? 8 : 0);
                int cc = wn * 32 + nt * 8 + ((lane & 3) << 1) + (q & 1);
                int i = tile * 128 + r;
                if (i < cnt) {
                    float s1 = acc1[mt][nt][q], s3 = acc3[mt][nt][q];
                    float h = (s1 / (1.0f + __expf(-s1))) * s3;
                    g_H[(size_t)(offs + i) * FF + n0 + cc] = h;
                }
            }
        }
    }
}

// ---------------- kernel 4: GEMM2 (H @ w2^T), BN=128, scaled scatter-add ----------------
__global__ __launch_bounds__(256, 2) void gemm2_kernel(const float* __restrict__ w2,
                                                       float* __restrict__ out) {
    int e, tile, cnt;
    if (!find_tile(blockIdx.x, e, tile, cnt)) return;
    int offs = g_offsets[e];
    int n0 = blockIdx.y * 128;

    __shared__ float As[2][2048];
    __shared__ float Bs[2][2048];
    __shared__ int   stok[128];
    __shared__ float scw[128];

    int tid = threadIdx.x;
    if (tid < 128) {
        int i = tile * 128 + tid;
        stok[tid] = (i < cnt) ? g_tok[e * NTOK + i] : -1;
        scw[tid]  = (i < cnt) ? g_cw[e * NTOK + i] : 0.0f;
    }
    __syncthreads();

    int warp = tid >> 5, lane = tid & 31;
    int wm = warp >> 1, wn = warp & 1;

    int ar0 = tid >> 2;
    int ar1 = ar0 + 64;
    int ac4 = (tid & 3) << 2;
    bool av0 = (tile * 128 + ar0) < cnt;
    bool av1 = (tile * 128 + ar1) < cnt;
    const float* ap0 = g_H + (size_t)(offs + tile * 128 + (av0 ? ar0 : 0)) * FF + ac4;
    const float* ap1 = g_H + (size_t)(offs + tile * 128 + (av1 ? ar1 : 0)) * FF + ac4;
    const float* bp0 = w2 + (size_t)e * DIM * FF + (size_t)(n0 + ar0) * FF + ac4;
    const float* bp1 = w2 + (size_t)e * DIM * FF + (size_t)(n0 + ar1) * FF + ac4;

    float4 ra0, ra1, rb0, rb1;
    auto load_k = [&](int k0) {
        ra0 = av0 ? *(const float4*)(ap0 + k0) : make_float4(0.f, 0.f, 0.f, 0.f);
        ra1 = av1 ? *(const float4*)(ap1 + k0) : make_float4(0.f, 0.f, 0.f, 0.f);
        rb0 = *(const float4*)(bp0 + k0);
        rb1 = *(const float4*)(bp1 + k0);
    };
    auto store_stage = [&](int s) {
        *(float4*)&As[s][swz(ar0, ac4)] = cvt4(ra0);
        *(float4*)&As[s][swz(ar1, ac4)] = cvt4(ra1);
        *(float4*)&Bs[s][swz(ar0, ac4)] = cvt4(rb0);
        *(float4*)&Bs[s][swz(ar1, ac4)] = cvt4(rb1);
    };

    float acc[2][8][4] = {};

    auto compute_stage = [&](int s) {
        const float* A = As[s];
        const float* B = Bs[s];
#pragma unroll
        for (int kk = 0; kk < 16; kk += 8) {
            float a[2][4];
#pragma unroll
            for (int mt = 0; mt < 2; mt++) {
                int r0 = wm * 32 + mt * 16 + (lane >> 2);
                int c  = kk + (lane & 3);
                a[mt][0] = A[swz(r0, c)];
                a[mt][1] = A[swz(r0 + 8, c)];
                a[mt][2] = A[swz(r0, c + 4)];
                a[mt][3] = A[swz(r0 + 8, c + 4)];
            }
#pragma unroll
            for (int nt = 0; nt < 8; nt++) {
                int cn = wn * 64 + nt * 8 + (lane >> 2);
                int kr = kk + (lane & 3);
                float b[2];
                b[0] = B[swz(cn, kr)]; b[1] = B[swz(cn, kr + 4)];
#pragma unroll
                for (int mt = 0; mt < 2; mt++)
                    mma8(acc[mt][nt], a[mt], b);
            }
        }
    };

    load_k(0);
    store_stage(0);
    __syncthreads();
#pragma unroll 1
    for (int kt = 0; kt < FF / 16; kt++) {
        int cur = kt & 1;
        if (kt + 1 < FF / 16) load_k((kt + 1) * 16);
        compute_stage(cur);
        if (kt + 1 < FF / 16) store_stage(cur ^ 1);
        __syncthreads();
    }

    // epilogue: out[token, n] += cw * acc  (2 commutative adds/elem -> deterministic)
#pragma unroll
    for (int mt = 0; mt < 2; mt++) {
#pragma unroll
        for (int nt = 0; nt < 8; nt++) {
#pragma unroll
            for (int q = 0; q < 4; q++) {
                int r  = wm * 32 + mt * 16 + (lane >> 2) + ((q >= 2) ? 8 : 0);
                int cc = wn * 64 + nt * 8 + ((lane & 3) << 1) + (q & 1);
                int i = tile * 128 + r;
                if (i < cnt) {
                    int t  = stok[r];
                    float w = scw[r];
                    atomicAdd(&out[(size_t)t * DIM + n0 + cc], acc[mt][nt][q] * w);
                }
            }
        }
    }
}

// ---------------- launch ----------------
extern "C" void kernel_launch(void* const* d_in, const int* in_sizes, int n_in,
                              void* d_out, int out_size) {
    const float* x  = (const float*)d_in[0];
    const float* gw = (const float*)d_in[1];
    const float* w1 = (const float*)d_in[2];
    const float* w2 = (const float*)d_in[3];
    const float* w3 = (const float*)d_in[4];
    float* out = (float*)d_out;

    zero_kernel<<<(out_size + 255) / 256, 256>>>(out, out_size);
    gate_kernel<<<NTOK / 8, 256>>>(x, gw);
    prefix_kernel<<<1, 32>>>();
    gemm1_kernel<<<dim3(264, FF / 64), 256>>>(x, w1, w3);
    gemm2_kernel<<<dim3(264, DIM / 128), 256>>>(w2, out);
}

// round 5
// speedup vs baseline: 2.6251x; 1.5417x over previous
#include <cuda_runtime.h>
#include <cstdint>
#include <math.h>

#define NE 8
#define NTOK 16384
#define DIM 1024
#define FF 2048

// ---------------- scratch (device globals; no allocation) ----------------
__device__ int   g_counts[NE];
__device__ int   g_offsets[NE + 1];
__device__ int   g_tok[NE * NTOK];
__device__ float g_cw[NE * NTOK];
__device__ float g_H[(size_t)2 * NTOK * FF];   // 256 MiB hidden activations

// ---------------- helpers ----------------
__device__ __forceinline__ unsigned f2tf(float f) {
    unsigned u;
    asm("cvt.rna.tf32.f32 %0, %1;" : "=r"(u) : "f"(f));
    return u;
}
__device__ __forceinline__ float f2tf_f(float f) { return __uint_as_float(f2tf(f)); }
__device__ __forceinline__ float4 cvt4(float4 v) {
    float4 r;
    r.x = f2tf_f(v.x); r.y = f2tf_f(v.y); r.z = f2tf_f(v.z); r.w = f2tf_f(v.w);
    return r;
}

static __device__ __forceinline__ uint32_t smem_u32(const void* p) {
    uint32_t a;
    asm("{ .reg .u64 t; cvta.to.shared.u64 t, %1; cvt.u32.u64 %0, t; }" : "=r"(a) : "l"(p));
    return a;
}

__device__ __forceinline__ void mma8u(float* c, const uint32_t* a, const uint32_t* b) {
    asm volatile(
        "mma.sync.aligned.m16n8k8.row.col.f32.tf32.tf32.f32 "
        "{%0,%1,%2,%3},{%4,%5,%6,%7},{%8,%9},{%0,%1,%2,%3};"
        : "+f"(c[0]), "+f"(c[1]), "+f"(c[2]), "+f"(c[3])
        : "r"(a[0]), "r"(a[1]), "r"(a[2]), "r"(a[3]), "r"(b[0]), "r"(b[1]));
}

#define LDSM4(r0_, r1_, r2_, r3_, addr)                                        \
    asm volatile("ldmatrix.sync.aligned.m8n8.x4.shared.b16 {%0,%1,%2,%3}, [%4];" \
        : "=r"(r0_), "=r"(r1_), "=r"(r2_), "=r"(r3_) : "r"(addr))

// Swizzled byte offset of 16B chunk: row r (64B rows = 16 floats), chunk base cb (0..3).
// chunk = cb ^ ((r>>1)&3): conflict-free for STS.128 phases AND ldmatrix 8-row phases.
__device__ __forceinline__ uint32_t swb(int r, int cb) {
    int chunk = (cb ^ (r >> 1)) & 3;
    return (uint32_t)(r * 64 + chunk * 16);
}

// ---------------- kernel 0: zero output + counts ----------------
__global__ void zero_kernel(float* out, int n) {
    int i = blockIdx.x * blockDim.x + threadIdx.x;
    if (i < n) out[i] = 0.0f;
    if (blockIdx.x == 0 && threadIdx.x < NE) g_counts[threadIdx.x] = 0;
}

// ---------------- kernel 1: gating + routing (one warp per token) ----------------
__global__ void gate_kernel(const float* __restrict__ x, const float* __restrict__ gw) {
    int warp = threadIdx.x >> 5;
    int lane = threadIdx.x & 31;
    int token = blockIdx.x * 8 + warp;

    const float* xr = x + (size_t)token * DIM;
    float xv[32];
#pragma unroll
    for (int j = 0; j < 32; j++) xv[j] = xr[j * 32 + lane];

    float logits[NE];
#pragma unroll
    for (int e = 0; e < NE; e++) {
        const float* g = gw + e * DIM;
        float s = 0.0f;
#pragma unroll
        for (int j = 0; j < 32; j++) s += xv[j] * g[j * 32 + lane];
#pragma unroll
        for (int o = 16; o; o >>= 1) s += __shfl_xor_sync(0xffffffffu, s, o);
        logits[e] = s;
    }

    if (lane == 0) {
        int i1 = 0;
#pragma unroll
        for (int e = 1; e < NE; e++)
            if (logits[e] > logits[i1]) i1 = e;
        int i2 = -1;
#pragma unroll
        for (int e = 0; e < NE; e++) {
            if (e == i1) continue;
            if (i2 < 0 || logits[e] > logits[i2]) i2 = e;
        }
        float p1 = 1.0f / (1.0f + __expf(logits[i2] - logits[i1]));
        float p2 = 1.0f - p1;
        int s1 = atomicAdd(&g_counts[i1], 1);
        g_tok[i1 * NTOK + s1] = token;
        g_cw[i1 * NTOK + s1]  = p1;
        int s2 = atomicAdd(&g_counts[i2], 1);
        g_tok[i2 * NTOK + s2] = token;
        g_cw[i2 * NTOK + s2]  = p2;
    }
}

// ---------------- kernel 2: prefix over 8 counts ----------------
__global__ void prefix_kernel() {
    if (threadIdx.x == 0) {
        int a = 0;
        for (int e = 0; e < NE; e++) { g_offsets[e] = a; a += g_counts[e]; }
        g_offsets[NE] = a;
    }
}

// ---------------- tile scheduler ----------------
__device__ __forceinline__ bool find_tile(int bx, int& e, int& tile, int& cnt) {
    int acc = 0;
    e = -1;
#pragma unroll
    for (int ee = 0; ee < NE; ee++) {
        int c = g_counts[ee];
        int t = (c + 127) >> 7;
        if (e < 0 && bx < acc + t) { e = ee; tile = bx - acc; cnt = c; }
        acc += t;
    }
    return e >= 0;
}

// ---------------- kernel 3: GEMM1 (x@w1^T, x@w3^T) -> silu*mul -> H ----------------
// BM=128, BN=64 (dual B), BK=16; double-buffered, tf32-converted SMEM, LDSM operand path
__global__ __launch_bounds__(256, 2) void gemm1_kernel(const float* __restrict__ x,
                                                       const float* __restrict__ w1,
                                                       const float* __restrict__ w3) {
    int e, tile, cnt;
    if (!find_tile(blockIdx.x, e, tile, cnt)) return;
    int offs = g_offsets[e];
    int n0 = blockIdx.y * 64;

    __shared__ float As[2][2048];
    __shared__ float B1s[2][1024];
    __shared__ float B3s[2][1024];
    __shared__ int   stok[128];

    int tid = threadIdx.x;
    if (tid < 128) {
        int i = tile * 128 + tid;
        stok[tid] = (i < cnt) ? g_tok[e * NTOK + i] : -1;
    }
    __syncthreads();

    int warp = tid >> 5, lane = tid & 31;
    int wm = warp >> 1, wn = warp & 1;

    // ---- global load coordinates ----
    int ar0 = tid >> 2;                 // A rows 0..63
    int ar1 = ar0 + 64;                 // A rows 64..127
    int acb = tid & 3;                  // chunk base (float col = acb*4)
    int ac4 = acb << 2;
    int t0 = stok[ar0], t1 = stok[ar1];
    const float* ap0 = x + (size_t)(t0 < 0 ? 0 : t0) * DIM + ac4;
    const float* ap1 = x + (size_t)(t1 < 0 ? 0 : t1) * DIM + ac4;
    const float* b1p = w1 + (size_t)e * FF * DIM + (size_t)(n0 + ar0) * DIM + ac4;
    const float* b3p = w3 + (size_t)e * FF * DIM + (size_t)(n0 + ar0) * DIM + ac4;

    // ---- SMEM byte bases + store offsets ----
    uint32_t As_b  = smem_u32(&As[0][0]);
    uint32_t B1s_b = smem_u32(&B1s[0][0]);
    uint32_t B3s_b = smem_u32(&B3s[0][0]);
    uint32_t stA0 = swb(ar0, acb), stA1 = swb(ar1, acb), stB = swb(ar0, acb);

    // ---- ldmatrix fragment offsets (hoisted; zero in-loop address math) ----
    // A: lanes 0-7 rows r0+, 8-15 rows r0+8, 16-23 rows r0 (col+4), 24-31 rows r0+8 (col+4)
    int arow = (((lane >> 3) & 1) << 3) + (lane & 7);
    int acol = lane >> 4;
    // B: lanes 0-7 rows n8+, 8-15 rows n8 (col+4), 16-23 rows n8+8, 24-31 rows n8+8 (col+4)
    int brow = (((lane >> 4) & 1) << 3) + (lane & 7);
    int bcol = (lane >> 3) & 1;
    uint32_t offA[2][2], offB[2][2];
#pragma unroll
    for (int mt = 0; mt < 2; mt++)
#pragma unroll
        for (int kki = 0; kki < 2; kki++)
            offA[mt][kki] = swb(wm * 32 + mt * 16 + arow, kki * 2 + acol);
#pragma unroll
    for (int p = 0; p < 2; p++)
#pragma unroll
        for (int kki = 0; kki < 2; kki++)
            offB[p][kki] = swb(wn * 32 + p * 16 + brow, kki * 2 + bcol);

    float4 ra0, ra1, rb1, rb3;
    auto load_k = [&](int k0) {
        ra0 = (t0 >= 0) ? *(const float4*)(ap0 + k0) : make_float4(0.f, 0.f, 0.f, 0.f);
        ra1 = (t1 >= 0) ? *(const float4*)(ap1 + k0) : make_float4(0.f, 0.f, 0.f, 0.f);
        rb1 = *(const float4*)(b1p + k0);
        rb3 = *(const float4*)(b3p + k0);
    };
    auto store_stage = [&](int s) {
        *(float4*)((char*)&As[s][0] + stA0)  = cvt4(ra0);
        *(float4*)((char*)&As[s][0] + stA1)  = cvt4(ra1);
        *(float4*)((char*)&B1s[s][0] + stB)  = cvt4(rb1);
        *(float4*)((char*)&B3s[s][0] + stB)  = cvt4(rb3);
    };

    float acc1[2][4][4] = {};
    float acc3[2][4][4] = {};

    auto compute_stage = [&](int s) {
        uint32_t aA  = As_b + s * 8192;
        uint32_t aB1 = B1s_b + s * 4096;
        uint32_t aB3 = B3s_b + s * 4096;
#pragma unroll
        for (int kki = 0; kki < 2; kki++) {
            uint32_t a[2][4];
            LDSM4(a[0][0], a[0][1], a[0][2], a[0][3], aA + offA[0][kki]);
            LDSM4(a[1][0], a[1][1], a[1][2], a[1][3], aA + offA[1][kki]);
#pragma unroll
            for (int p = 0; p < 2; p++) {
                uint32_t b1[4], b3[4];
                LDSM4(b1[0], b1[1], b1[2], b1[3], aB1 + offB[p][kki]);
                LDSM4(b3[0], b3[1], b3[2], b3[3], aB3 + offB[p][kki]);
#pragma unroll
                for (int mt = 0; mt < 2; mt++) {
                    mma8u(acc1[mt][2 * p],     a[mt], &b1[0]);
                    mma8u(acc1[mt][2 * p + 1], a[mt], &b1[2]);
                    mma8u(acc3[mt][2 * p],     a[mt], &b3[0]);
                    mma8u(acc3[mt][2 * p + 1], a[mt], &b3[2]);
                }
            }
        }
    };

    load_k(0);
    store_stage(0);
    __syncthreads();
#pragma unroll 1
    for (int kt = 0; kt < DIM / 16; kt++) {
        int cur = kt & 1;
        if (kt + 1 < DIM / 16) load_k((kt + 1) * 16);
        compute_stage(cur);
        if (kt + 1 < DIM / 16) store_stage(cur ^ 1);
        __syncthreads();
    }

    // epilogue: h = silu(s1) * s3 -> g_H
#pragma unroll
    for (int mt = 0; mt < 2; mt++) {
#pragma unroll
        for (int nt = 0; nt < 4; nt++) {
#pragma unroll
            for (int q = 0; q < 4; q++) {
                int r  = wm * 32 + mt * 16 + (lane >> 2) + ((q >= 2) ? 8 : 0);
                int cc = wn * 32 + nt * 8 + ((lane & 3) << 1) + (q & 1);
                int i = tile * 128 + r;
                if (i < cnt) {
                    float s1 = acc1[mt][nt][q], s3 = acc3[mt][nt][q];
                    float h = (s1 / (1.0f + __expf(-s1))) * s3;
                    g_H[(size_t)(offs + i) * FF + n0 + cc] = h;
                }
            }
        }
    }
}

// ---------------- kernel 4: GEMM2 (H @ w2^T), BN=128, scaled scatter-add ----------------
__global__ __launch_bounds__(256, 2) void gemm2_kernel(const float* __restrict__ w2,
                                                       float* __restrict__ out) {
    int e, tile, cnt;
    if (!find_tile(blockIdx.x, e, tile, cnt)) return;
    int offs = g_offsets[e];
    int n0 = blockIdx.y * 128;

    __shared__ float As[2][2048];
    __shared__ float Bs[2][2048];
    __shared__ int   stok[128];
    __shared__ float scw[128];

    int tid = threadIdx.x;
    if (tid < 128) {
        int i = tile * 128 + tid;
        stok[tid] = (i < cnt) ? g_tok[e * NTOK + i] : -1;
        scw[tid]  = (i < cnt) ? g_cw[e * NTOK + i] : 0.0f;
    }
    __syncthreads();

    int warp = tid >> 5, lane = tid & 31;
    int wm = warp >> 1, wn = warp & 1;

    int ar0 = tid >> 2;
    int ar1 = ar0 + 64;
    int acb = tid & 3;
    int ac4 = acb << 2;
    bool av0 = (tile * 128 + ar0) < cnt;
    bool av1 = (tile * 128 + ar1) < cnt;
    const float* ap0 = g_H + (size_t)(offs + tile * 128 + (av0 ? ar0 : 0)) * FF + ac4;
    const float* ap1 = g_H + (size_t)(offs + tile * 128 + (av1 ? ar1 : 0)) * FF + ac4;
    const float* bp0 = w2 + (size_t)e * DIM * FF + (size_t)(n0 + ar0) * FF + ac4;
    const float* bp1 = w2 + (size_t)e * DIM * FF + (size_t)(n0 + ar1) * FF + ac4;

    uint32_t As_b = smem_u32(&As[0][0]);
    uint32_t Bs_b = smem_u32(&Bs[0][0]);
    uint32_t stA0 = swb(ar0, acb), stA1 = swb(ar1, acb);

    int arow = (((lane >> 3) & 1) << 3) + (lane & 7);
    int acol = lane >> 4;
    int brow = (((lane >> 4) & 1) << 3) + (lane & 7);
    int bcol = (lane >> 3) & 1;
    uint32_t offA[2][2], offB[4][2];
#pragma unroll
    for (int mt = 0; mt < 2; mt++)
#pragma unroll
        for (int kki = 0; kki < 2; kki++)
            offA[mt][kki] = swb(wm * 32 + mt * 16 + arow, kki * 2 + acol);
#pragma unroll
    for (int p = 0; p < 4; p++)
#pragma unroll
        for (int kki = 0; kki < 2; kki++)
            offB[p][kki] = swb(wn * 64 + p * 16 + brow, kki * 2 + bcol);

    float4 ra0, ra1, rb0, rb1;
    auto load_k = [&](int k0) {
        ra0 = av0 ? *(const float4*)(ap0 + k0) : make_float4(0.f, 0.f, 0.f, 0.f);
        ra1 = av1 ? *(const float4*)(ap1 + k0) : make_float4(0.f, 0.f, 0.f, 0.f);
        rb0 = *(const float4*)(bp0 + k0);
        rb1 = *(const float4*)(bp1 + k0);
    };
    auto store_stage = [&](int s) {
        *(float4*)((char*)&As[s][0] + stA0) = cvt4(ra0);
        *(float4*)((char*)&As[s][0] + stA1) = cvt4(ra1);
        *(float4*)((char*)&Bs[s][0] + stA0) = cvt4(rb0);
        *(float4*)((char*)&Bs[s][0] + stA1) = cvt4(rb1);
    };

    float acc[2][8][4] = {};

    auto compute_stage = [&](int s) {
        uint32_t aA = As_b + s * 8192;
        uint32_t aB = Bs_b + s * 8192;
#pragma unroll
        for (int kki = 0; kki < 2; kki++) {
            uint32_t a[2][4];
            LDSM4(a[0][0], a[0][1], a[0][2], a[0][3], aA + offA[0][kki]);
            LDSM4(a[1][0], a[1][1], a[1][2], a[1][3], aA + offA[1][kki]);
#pragma unroll
            for (int p = 0; p < 4; p++) {
                uint32_t b[4];
                LDSM4(b[0], b[1], b[2], b[3], aB + offB[p][kki]);
#pragma unroll
                for (int mt = 0; mt < 2; mt++) {
                    mma8u(acc[mt][2 * p],     a[mt], &b[0]);
                    mma8u(acc[mt][2 * p + 1], a[mt], &b[2]);
                }
            }
        }
    };

    load_k(0);
    store_stage(0);
    __syncthreads();
#pragma unroll 1
    for (int kt = 0; kt < FF / 16; kt++) {
        int cur = kt & 1;
        if (kt + 1 < FF / 16) load_k((kt + 1) * 16);
        compute_stage(cur);
        if (kt + 1 < FF / 16) store_stage(cur ^ 1);
        __syncthreads();
    }

    // epilogue: out[token, n] += cw * acc  (2 commutative adds/elem -> deterministic)
#pragma unroll
    for (int mt = 0; mt < 2; mt++) {
#pragma unroll
        for (int nt = 0; nt < 8; nt++) {
#pragma unroll
            for (int q = 0; q < 4; q++) {
                int r  = wm * 32 + mt * 16 + (lane >> 2) + ((q >= 2) ? 8 : 0);
                int cc = wn * 64 + nt * 8 + ((lane & 3) << 1) + (q & 1);
                int i = tile * 128 + r;
                if (i < cnt) {
                    int t  = stok[r];
                    float w = scw[r];
                    atomicAdd(&out[(size_t)t * DIM + n0 + cc], acc[mt][nt][q] * w);
                }
            }
        }
    }
}

// ---------------- launch ----------------
extern "C" void kernel_launch(void* const* d_in, const int* in_sizes, int n_in,
                              void* d_out, int out_size) {
    const float* x  = (const float*)d_in[0];
    const float* gw = (const float*)d_in[1];
    const float* w1 = (const float*)d_in[2];
    const float* w2 = (const float*)d_in[3];
    const float* w3 = (const float*)d_in[4];
    float* out = (float*)d_out;

    zero_kernel<<<(out_size + 255) / 256, 256>>>(out, out_size);
    gate_kernel<<<NTOK / 8, 256>>>(x, gw);
    prefix_kernel<<<1, 32>>>();
    gemm1_kernel<<<dim3(264, FF / 64), 256>>>(x, w1, w3);
    gemm2_kernel<<<dim3(264, DIM / 128), 256>>>(w2, out);
}